// round 13
// baseline (speedup 1.0000x reference)
#include <cuda_runtime.h>
#include <math.h>
#include <stdint.h>

#define BB 16
#define CC 128
#define HW 4096
#define NHEAD 8
#define HDIM 16
#define BH 128
#define OC3 384
#define OUTC 512

// Scratch (allocation-free rule: __device__ globals)
__device__ float g_s[(size_t)BB * CC * HW];        // CPE output
__device__ float g_qkv[(size_t)BB * OC3 * HW];     // qkv per batch [384][4096]
__device__ float g_cat[(size_t)BB * 2 * CC * HW];  // [res1 | src*ca] per batch [256][4096]
__device__ float g_pool[BB * CC];
__device__ float g_wqkvT[CC * OC3];                // W_qkv^T [128][384]
__device__ float g_woutT[2 * CC * OUTC];           // W_out^T [256][512]
__device__ float g_lacc[BH * 8 * 256];             // lambda partials (unnormalized)
__device__ float g_lm[BH * 8 * HDIM];
__device__ float g_ld[BH * 8 * HDIM];

__device__ __forceinline__ uint32_t smem_u32(const void* p) {
    uint32_t a;
    asm("{ .reg .u64 tmp; cvta.to.shared.u64 tmp, %1; cvt.u32.u64 %0, tmp; }"
        : "=r"(a) : "l"(p));
    return a;
}
__device__ __forceinline__ void cp_async16(uint32_t dst, const void* src) {
    asm volatile("cp.async.cg.shared.global [%0], [%1], 16;" :: "r"(dst), "l"(src) : "memory");
}

// ---------------- both weight transposes in one launch ----------------
__global__ void k_transpose_all(const float* __restrict__ qkvw,
                                const float* __restrict__ outw) {
    int idx = blockIdx.x * 256 + threadIdx.x;
    if (idx < OC3 * CC) {
        int o = idx / CC, k = idx - o * CC;
        g_wqkvT[k * OC3 + o] = qkvw[idx];
    }
    int idx2 = idx - OC3 * CC;
    if (idx2 >= 0 && idx2 < OUTC * 2 * CC) {
        int o = idx2 / (2 * CC), k = idx2 - o * (2 * CC);
        g_woutT[k * OUTC + o] = outw[idx2];
    }
}

// ====== double-buffered 128x128x32 GEMM, 256 threads, 8x8 micro, single sync/chunk ======
// Out[b][o][n] = sum_k Wt[k][o] * Bmat[b][k][n]   (Wt pre-transposed, row stride Mtot)
#define AS_OFF 0
#define IS_OFF 32768
#define GEMM_SMEM 65536

__global__ void __launch_bounds__(256, 2) k_gemm(const float* __restrict__ Wt,
                                                 const float* __restrict__ Bbase,
                                                 float* __restrict__ Obase,
                                                 int KC, int Mtot) {
    extern __shared__ char sm[];
    float* As = (float*)(sm + AS_OFF);       // [2][32][128]
    float* Is = (float*)(sm + IS_OFF);       // [2][32][128]
    uint32_t as_u32 = smem_u32(As);
    uint32_t is_u32 = smem_u32(Is);

    int b = blockIdx.z;
    int o0 = blockIdx.y * 128;
    int n0 = blockIdx.x * 128;
    int tid = threadIdx.x, tx = tid & 15, ty = tid >> 4;
    int bk = tid >> 3, bn = (tid & 7) * 4;   // loaders: 8 threads/row, 4x float4 each

    const float* Bb = Bbase + (size_t)b * KC * HW;
    int nchunk = KC >> 5;

    // prologue: chunk 0 -> buf0
#pragma unroll
    for (int u = 0; u < 4; u++) {
        cp_async16(as_u32 + (uint32_t)(bk * 512 + (bn + u * 32) * 4),
                   Wt + (size_t)bk * Mtot + o0 + bn + u * 32);
        cp_async16(is_u32 + (uint32_t)(bk * 512 + (bn + u * 32) * 4),
                   Bb + (size_t)bk * HW + n0 + bn + u * 32);
    }
    asm volatile("cp.async.commit_group;" ::: "memory");

    float acc[8][8] = {};
    int buf = 0;
    for (int ch = 0; ch < nchunk; ch++) {
        asm volatile("cp.async.wait_group 0;" ::: "memory");
        __syncthreads();   // chunk data ready AND all warps done with the other buffer
        if (ch + 1 < nchunk) {
            int k0n = (ch + 1) << 5;
            uint32_t boff = (uint32_t)((buf ^ 1) * 16384);
            const float* arow = Wt + (size_t)(k0n + bk) * Mtot + o0;
            const float* srow = Bb + (size_t)(k0n + bk) * HW + n0;
#pragma unroll
            for (int u = 0; u < 4; u++) {
                cp_async16(as_u32 + boff + (uint32_t)(bk * 512 + (bn + u * 32) * 4),
                           arow + bn + u * 32);
                cp_async16(is_u32 + boff + (uint32_t)(bk * 512 + (bn + u * 32) * 4),
                           srow + bn + u * 32);
            }
            asm volatile("cp.async.commit_group;" ::: "memory");
        }
        const float* Ab = As + buf * (32 * 128);
        const float* Ib = Is + buf * (32 * 128);
#pragma unroll
        for (int kk = 0; kk < 32; kk++) {
            float4 a0 = *(const float4*)(Ab + kk * 128 + ty * 4);
            float4 a1 = *(const float4*)(Ab + kk * 128 + ty * 4 + 64);
            float4 b0 = *(const float4*)(Ib + kk * 128 + tx * 4);
            float4 b1 = *(const float4*)(Ib + kk * 128 + tx * 4 + 64);
            float ar[8] = {a0.x, a0.y, a0.z, a0.w, a1.x, a1.y, a1.z, a1.w};
            float br[8] = {b0.x, b0.y, b0.z, b0.w, b1.x, b1.y, b1.z, b1.w};
#pragma unroll
            for (int i = 0; i < 8; i++)
#pragma unroll
                for (int j = 0; j < 8; j++)
                    acc[i][j] += ar[i] * br[j];
        }
        buf ^= 1;
    }
    float* Ob = Obase + (size_t)b * Mtot * HW;
#pragma unroll
    for (int i = 0; i < 8; i++) {
        int row = o0 + ((i < 4) ? (ty * 4 + i) : (ty * 4 + 64 + i - 4));
        float4 v0 = make_float4(acc[i][0], acc[i][1], acc[i][2], acc[i][3]);
        float4 v1 = make_float4(acc[i][4], acc[i][5], acc[i][6], acc[i][7]);
        *(float4*)(Ob + (size_t)row * HW + n0 + tx * 4) = v0;
        *(float4*)(Ob + (size_t)row * HW + n0 + tx * 4 + 64) = v1;
    }
}

// ---------------- CPE: depthwise 3x3 + residual, fused global-mean pool ----------------
__global__ void k_cpe(const float* __restrict__ src, const float* __restrict__ cpe_w) {
    int bc = blockIdx.x;              // b*C + c
    int c = bc & (CC - 1);
    const float* plane = src + (size_t)bc * HW;
    __shared__ float t[66][66];
    __shared__ float red[8];
    for (int i = threadIdx.x; i < 66 * 66; i += blockDim.x) {
        int r = i / 66, q = i % 66;
        int rr = r - 1, qq = q - 1;
        t[r][q] = (rr >= 0 && rr < 64 && qq >= 0 && qq < 64) ? plane[rr * 64 + qq] : 0.f;
    }
    __syncthreads();
    float w[9];
#pragma unroll
    for (int j = 0; j < 9; j++) w[j] = cpe_w[c * 9 + j];
    float psum = 0.f;
    for (int p = threadIdx.x; p < HW; p += blockDim.x) {
        int r = p >> 6, q = p & 63;
        float center = t[r + 1][q + 1];
        psum += center;
        float acc = center;  // residual
#pragma unroll
        for (int dr = 0; dr < 3; dr++)
#pragma unroll
            for (int dc = 0; dc < 3; dc++)
                acc += w[dr * 3 + dc] * t[r + dr][q + dc];
        g_s[(size_t)bc * HW + p] = acc;
    }
#pragma unroll
    for (int off = 16; off; off >>= 1) psum += __shfl_down_sync(0xffffffffu, psum, off);
    if ((threadIdx.x & 31) == 0) red[threadIdx.x >> 5] = psum;
    __syncthreads();
    if (threadIdx.x < 8) {
        psum = red[threadIdx.x];
#pragma unroll
        for (int off = 4; off; off >>= 1) psum += __shfl_down_sync(0xffu, psum, off);
        if (threadIdx.x == 0) g_pool[bc] = psum * (1.f / HW);
    }
}

// -------- scale second half of cat (ECA computed inline): g_cat[b][128+c] = src * ca --------
__global__ void k_scale(const float* __restrict__ src, const float* __restrict__ w3) {
    int bc = blockIdx.x;
    int b = bc >> 7, c = bc & 127;
    float x0 = (c > 0) ? g_pool[bc - 1] : 0.f;
    float x1 = g_pool[bc];
    float x2 = (c < CC - 1) ? g_pool[bc + 1] : 0.f;
    float z = w3[0] * x0 + w3[1] * x1 + w3[2] * x2;
    float ca = 1.f / (1.f + expf(-z));
    const float* ip = src + (size_t)bc * HW;
    float* op = g_cat + ((size_t)b * 2 * CC + CC + c) * HW;
    for (int p = threadIdx.x * 4; p < HW; p += 256 * 4) {
        float4 v = *(const float4*)(ip + p);
        v.x *= ca; v.y *= ca; v.z *= ca; v.w *= ca;
        *(float4*)(op + p) = v;
    }
}

// ---------- content_lambda phase 1: per-512-col partial online softmax ----------
__global__ void k_lambda_part() {
    int blk = blockIdx.x;
    int bh = blk >> 3, chunk = blk & 7;
    int b = bh >> 3, nh = bh & 7;
    const float* kbase = g_qkv + ((size_t)b * OC3 + CC + nh * HDIM) * HW + chunk * 512;
    const float* vbase = g_qkv + ((size_t)b * OC3 + 2 * CC + nh * HDIM) * HW + chunk * 512;
    __shared__ float ks[HDIM][129];
    __shared__ float vs[HDIM][129];
    int tid = threadIdx.x;
    int i = tid >> 4, o = tid & 15;
    float m = -1e30f, d = 0.f, acc = 0.f;
    for (int c0 = 0; c0 < 512; c0 += 128) {
        for (int t = tid; t < HDIM * 128; t += 256) {
            int r = t >> 7, j = t & 127;
            ks[r][j] = kbase[(size_t)r * HW + c0 + j];
            vs[r][j] = vbase[(size_t)r * HW + c0 + j];
        }
        __syncthreads();
        float mc = -1e30f;
#pragma unroll
        for (int t = 0; t < 8; t++) mc = fmaxf(mc, ks[i][o + t * 16]);
#pragma unroll
        for (int msk = 1; msk < 16; msk <<= 1)
            mc = fmaxf(mc, __shfl_xor_sync(0xffffffffu, mc, msk));
        float mnew = fmaxf(m, mc);
        float corr = expf(m - mnew);
        d *= corr; acc *= corr;
        float ps = 0.f;
#pragma unroll
        for (int t = 0; t < 8; t++) {
            float e = expf(ks[i][o + t * 16] - mnew);
            ks[i][o + t * 16] = e;
            ps += e;
        }
#pragma unroll
        for (int msk = 1; msk < 16; msk <<= 1)
            ps += __shfl_xor_sync(0xffffffffu, ps, msk);
        d += ps;
        m = mnew;
        __syncwarp();
#pragma unroll 8
        for (int j = 0; j < 128; j++) acc += ks[i][j] * vs[o][j];
        __syncthreads();
    }
    g_lacc[blk * 256 + tid] = acc;
    if (o == 0) {
        g_lm[blk * HDIM + i] = m;
        g_ld[blk * HDIM + i] = d;
    }
}

// ====== fused: lambda merge + position 5x5 conv + combine -> g_cat[0:128] ======
// grid (4 bands x BH); smem: vt[16][20][68] + rel[16][25] + lam[16][17]
#define VT_ELEMS (16 * 20 * 68)
#define POS_SMEM ((VT_ELEMS + 400 + 16 * 17) * 4)

__global__ void __launch_bounds__(256, 2) k_poscomb(const float* __restrict__ rel) {
    extern __shared__ float smf[];
    float* vt = smf;                        // [o][r][q] : o*1360 + r*68 + q
    float* rel_s = smf + VT_ELEMS;          // [16][25]
    float* lam_s = rel_s + 400;             // [16][17]
    int band = blockIdx.x, bh = blockIdx.y;
    int b = bh >> 3, nh = bh & 7;
    int tid = threadIdx.x;
    const float* vbase = g_qkv + ((size_t)b * OC3 + 2 * CC + nh * HDIM) * HW;

    // load v halos for the 16 channels of this head
    for (int e = tid; e < VT_ELEMS; e += 256) {
        int o = e / 1360, rem = e - o * 1360;
        int r = rem / 68, q = rem - r * 68;
        int gr = band * 16 + r - 2, gc = q - 2;
        float v = 0.f;
        if (gr >= 0 && gr < 64 && gc >= 0 && gc < 64)
            v = vbase[(size_t)o * HW + gr * 64 + gc];
        vt[e] = v;
    }
    for (int e = tid; e < 400; e += 256) rel_s[e] = rel[e];
    // lambda merge (same math as old k_lambda_merge)
    {
        int i = tid >> 4, o = tid & 15;
        float M = -1e30f;
#pragma unroll
        for (int c = 0; c < 8; c++) M = fmaxf(M, g_lm[(bh * 8 + c) * HDIM + i]);
        float acc = 0.f, d = 0.f;
#pragma unroll
        for (int c = 0; c < 8; c++) {
            float w = expf(g_lm[(bh * 8 + c) * HDIM + i] - M);
            acc += g_lacc[(bh * 8 + c) * 256 + tid] * w;
            d += g_ld[(bh * 8 + c) * HDIM + i] * w;
        }
        lam_s[i * 17 + o] = acc / d;
    }
    __syncthreads();

    const float* qbase = g_qkv + ((size_t)b * OC3 + nh * HDIM) * HW;
    float* rbase = g_cat + ((size_t)b * 2 * CC + nh * HDIM) * HW;
    const float scaling = 0.25f;  // HD^-0.5
#pragma unroll
    for (int p = 0; p < 4; p++) {
        int px = tid + p * 256;              // 0..1023 within band
        int lr = px >> 6, lc = px & 63;
        int gpix = (band * 16 + lr) * 64 + lc;
        float qv[16];
#pragma unroll
        for (int i2 = 0; i2 < 16; i2++) qv[i2] = qbase[(size_t)i2 * HW + gpix];
#pragma unroll
        for (int o = 0; o < 16; o++) {
            const float* w = rel_s + o * 25;
            const float* vb = vt + o * 1360 + lr * 68 + lc;
            float pl = 0.f;
#pragma unroll
            for (int dr = 0; dr < 5; dr++)
#pragma unroll
                for (int dc = 0; dc < 5; dc++)
                    pl += w[dr * 5 + dc] * vb[dr * 68 + dc];
            float cacc = 0.f;
#pragma unroll
            for (int i2 = 0; i2 < 16; i2++) cacc += qv[i2] * lam_s[i2 * 17 + o];
            rbase[(size_t)o * HW + gpix] = cacc * scaling + qv[o] * pl;
        }
    }
}

extern "C" void kernel_launch(void* const* d_in, const int* in_sizes, int n_in,
                              void* d_out, int out_size) {
    const float* src    = (const float*)d_in[0];  // (16,128,64,64)
    const float* cpe_w  = (const float*)d_in[1];  // (128,1,3,3)
    const float* qkv_w  = (const float*)d_in[2];  // (384,128)
    const float* rel    = (const float*)d_in[3];  // (16,5,5)
    const float* c1d    = (const float*)d_in[4];  // (3,)
    const float* out_w  = (const float*)d_in[5];  // (512,256)
    float* out = (float*)d_out;                   // (16,512,64,64)

    cudaFuncSetAttribute(k_gemm, cudaFuncAttributeMaxDynamicSharedMemorySize, GEMM_SMEM);
    cudaFuncSetAttribute(k_poscomb, cudaFuncAttributeMaxDynamicSharedMemorySize, POS_SMEM);

    float* d_s;      cudaGetSymbolAddress((void**)&d_s, g_s);
    float* d_qkv;    cudaGetSymbolAddress((void**)&d_qkv, g_qkv);
    float* d_cat;    cudaGetSymbolAddress((void**)&d_cat, g_cat);
    float* d_wqkvT;  cudaGetSymbolAddress((void**)&d_wqkvT, g_wqkvT);
    float* d_woutT;  cudaGetSymbolAddress((void**)&d_woutT, g_woutT);

    k_transpose_all<<<(OC3 * CC + OUTC * 2 * CC + 255) / 256, 256>>>(qkv_w, out_w);
    k_cpe<<<BB * CC, 256>>>(src, cpe_w);
    k_scale<<<BB * CC, 256>>>(src, c1d);
    // QKV GEMM: M=384, N=4096, K=128
    k_gemm<<<dim3(HW / 128, OC3 / 128, BB), 256, GEMM_SMEM>>>(d_wqkvT, d_s, d_qkv, CC, OC3);
    k_lambda_part<<<BH * 8, 256>>>();
    k_poscomb<<<dim3(4, BH), 256, POS_SMEM>>>(rel);
    // Final GEMM: M=512, N=4096, K=256 over g_cat
    k_gemm<<<dim3(HW / 128, OUTC / 128, BB), 256, GEMM_SMEM>>>(d_woutT, d_cat, out, 2 * CC, OUTC);
}

// round 16
// speedup vs baseline: 1.3350x; 1.3350x over previous
#include <cuda_runtime.h>
#include <math.h>
#include <stdint.h>

#define BB 16
#define CC 128
#define HW 4096
#define NHEAD 8
#define HDIM 16
#define BH 128
#define OC3 384
#define OUTC 512

// Scratch (allocation-free rule: __device__ globals)
__device__ float g_s[(size_t)BB * CC * HW];        // CPE output
__device__ float g_qkv[(size_t)BB * OC3 * HW];     // qkv per batch [384][4096]
__device__ float g_poslam[(size_t)BB * CC * HW];   // position lambda
__device__ float g_cat[(size_t)BB * 2 * CC * HW];  // [res1 | src*ca] per batch [256][4096]
__device__ float g_pool[BB * CC];
__device__ float g_lam[BH * HDIM * HDIM];
__device__ float g_wqkvT[CC * OC3];                // W_qkv^T [128][384]
__device__ float g_woutT[2 * CC * OUTC];           // W_out^T [256][512]
__device__ float g_lacc[BH * 8 * 256];             // lambda partials (unnormalized)
__device__ float g_lm[BH * 8 * HDIM];
__device__ float g_ld[BH * 8 * HDIM];

__device__ __forceinline__ uint32_t smem_u32(const void* p) {
    uint32_t a;
    asm("{ .reg .u64 tmp; cvta.to.shared.u64 tmp, %1; cvt.u32.u64 %0, tmp; }"
        : "=r"(a) : "l"(p));
    return a;
}
__device__ __forceinline__ void cp_async16(uint32_t dst, const void* src) {
    asm volatile("cp.async.cg.shared.global [%0], [%1], 16;" :: "r"(dst), "l"(src) : "memory");
}

// ---------------- both weight transposes in one launch ----------------
__global__ void k_transpose_all(const float* __restrict__ qkvw,
                                const float* __restrict__ outw) {
    int idx = blockIdx.x * 256 + threadIdx.x;
    if (idx < OC3 * CC) {
        int o = idx / CC, k = idx - o * CC;
        g_wqkvT[k * OC3 + o] = qkvw[idx];
    }
    int idx2 = idx - OC3 * CC;
    if (idx2 >= 0 && idx2 < OUTC * 2 * CC) {
        int o = idx2 / (2 * CC), k = idx2 - o * (2 * CC);
        g_woutT[k * OUTC + o] = outw[idx2];
    }
}

// ====== double-buffered 128x128x32 GEMM, 256 threads, 8x8 micro, single sync/chunk ======
// Out[b][o][n] = sum_k Wt[k][o] * Bmat[b][k][n]   (Wt pre-transposed, row stride Mtot)
#define AS_OFF 0
#define IS_OFF 32768
#define GEMM_SMEM 65536

__global__ void __launch_bounds__(256, 2) k_gemm(const float* __restrict__ Wt,
                                                 const float* __restrict__ Bbase,
                                                 float* __restrict__ Obase,
                                                 int KC, int Mtot) {
    extern __shared__ char sm[];
    float* As = (float*)(sm + AS_OFF);       // [2][32][128]
    float* Is = (float*)(sm + IS_OFF);       // [2][32][128]
    uint32_t as_u32 = smem_u32(As);
    uint32_t is_u32 = smem_u32(Is);

    int b = blockIdx.z;
    int o0 = blockIdx.y * 128;
    int n0 = blockIdx.x * 128;
    int tid = threadIdx.x, tx = tid & 15, ty = tid >> 4;
    int bk = tid >> 3, bn = (tid & 7) * 4;   // loaders: 8 threads/row, 4x float4 each

    const float* Bb = Bbase + (size_t)b * KC * HW;
    int nchunk = KC >> 5;

    // prologue: chunk 0 -> buf0
#pragma unroll
    for (int u = 0; u < 4; u++) {
        cp_async16(as_u32 + (uint32_t)(bk * 512 + (bn + u * 32) * 4),
                   Wt + (size_t)bk * Mtot + o0 + bn + u * 32);
        cp_async16(is_u32 + (uint32_t)(bk * 512 + (bn + u * 32) * 4),
                   Bb + (size_t)bk * HW + n0 + bn + u * 32);
    }
    asm volatile("cp.async.commit_group;" ::: "memory");

    float acc[8][8] = {};
    int buf = 0;
    for (int ch = 0; ch < nchunk; ch++) {
        asm volatile("cp.async.wait_group 0;" ::: "memory");
        __syncthreads();   // chunk data ready AND all warps done with the other buffer
        if (ch + 1 < nchunk) {
            int k0n = (ch + 1) << 5;
            uint32_t boff = (uint32_t)((buf ^ 1) * 16384);
            const float* arow = Wt + (size_t)(k0n + bk) * Mtot + o0;
            const float* srow = Bb + (size_t)(k0n + bk) * HW + n0;
#pragma unroll
            for (int u = 0; u < 4; u++) {
                cp_async16(as_u32 + boff + (uint32_t)(bk * 512 + (bn + u * 32) * 4),
                           arow + bn + u * 32);
                cp_async16(is_u32 + boff + (uint32_t)(bk * 512 + (bn + u * 32) * 4),
                           srow + bn + u * 32);
            }
            asm volatile("cp.async.commit_group;" ::: "memory");
        }
        const float* Ab = As + buf * (32 * 128);
        const float* Ib = Is + buf * (32 * 128);
#pragma unroll
        for (int kk = 0; kk < 32; kk++) {
            float4 a0 = *(const float4*)(Ab + kk * 128 + ty * 4);
            float4 a1 = *(const float4*)(Ab + kk * 128 + ty * 4 + 64);
            float4 b0 = *(const float4*)(Ib + kk * 128 + tx * 4);
            float4 b1 = *(const float4*)(Ib + kk * 128 + tx * 4 + 64);
            float ar[8] = {a0.x, a0.y, a0.z, a0.w, a1.x, a1.y, a1.z, a1.w};
            float br[8] = {b0.x, b0.y, b0.z, b0.w, b1.x, b1.y, b1.z, b1.w};
#pragma unroll
            for (int i = 0; i < 8; i++)
#pragma unroll
                for (int j = 0; j < 8; j++)
                    acc[i][j] += ar[i] * br[j];
        }
        buf ^= 1;
    }
    float* Ob = Obase + (size_t)b * Mtot * HW;
#pragma unroll
    for (int i = 0; i < 8; i++) {
        int row = o0 + ((i < 4) ? (ty * 4 + i) : (ty * 4 + 64 + i - 4));
        float4 v0 = make_float4(acc[i][0], acc[i][1], acc[i][2], acc[i][3]);
        float4 v1 = make_float4(acc[i][4], acc[i][5], acc[i][6], acc[i][7]);
        *(float4*)(Ob + (size_t)row * HW + n0 + tx * 4) = v0;
        *(float4*)(Ob + (size_t)row * HW + n0 + tx * 4 + 64) = v1;
    }
}

// ---------------- CPE: depthwise 3x3 + residual, fused global-mean pool ----------------
__global__ void k_cpe(const float* __restrict__ src, const float* __restrict__ cpe_w) {
    int bc = blockIdx.x;              // b*C + c
    int c = bc & (CC - 1);
    const float* plane = src + (size_t)bc * HW;
    __shared__ float t[66][66];
    __shared__ float red[8];
    for (int i = threadIdx.x; i < 66 * 66; i += blockDim.x) {
        int r = i / 66, q = i % 66;
        int rr = r - 1, qq = q - 1;
        t[r][q] = (rr >= 0 && rr < 64 && qq >= 0 && qq < 64) ? plane[rr * 64 + qq] : 0.f;
    }
    __syncthreads();
    float w[9];
#pragma unroll
    for (int j = 0; j < 9; j++) w[j] = cpe_w[c * 9 + j];
    float psum = 0.f;
    for (int p = threadIdx.x; p < HW; p += blockDim.x) {
        int r = p >> 6, q = p & 63;
        float center = t[r + 1][q + 1];
        psum += center;
        float acc = center;  // residual
#pragma unroll
        for (int dr = 0; dr < 3; dr++)
#pragma unroll
            for (int dc = 0; dc < 3; dc++)
                acc += w[dr * 3 + dc] * t[r + dr][q + dc];
        g_s[(size_t)bc * HW + p] = acc;
    }
#pragma unroll
    for (int off = 16; off; off >>= 1) psum += __shfl_down_sync(0xffffffffu, psum, off);
    if ((threadIdx.x & 31) == 0) red[threadIdx.x >> 5] = psum;
    __syncthreads();
    if (threadIdx.x < 8) {
        psum = red[threadIdx.x];
#pragma unroll
        for (int off = 4; off; off >>= 1) psum += __shfl_down_sync(0xffu, psum, off);
        if (threadIdx.x == 0) g_pool[bc] = psum * (1.f / HW);
    }
}

// -------- scale second half of cat (ECA computed inline): g_cat[b][128+c] = src * ca --------
__global__ void k_scale(const float* __restrict__ src, const float* __restrict__ w3) {
    int bc = blockIdx.x;
    int b = bc >> 7, c = bc & 127;
    float x0 = (c > 0) ? g_pool[bc - 1] : 0.f;
    float x1 = g_pool[bc];
    float x2 = (c < CC - 1) ? g_pool[bc + 1] : 0.f;
    float z = w3[0] * x0 + w3[1] * x1 + w3[2] * x2;
    float ca = 1.f / (1.f + expf(-z));
    const float* ip = src + (size_t)bc * HW;
    float* op = g_cat + ((size_t)b * 2 * CC + CC + c) * HW;
    for (int p = threadIdx.x * 4; p < HW; p += 256 * 4) {
        float4 v = *(const float4*)(ip + p);
        v.x *= ca; v.y *= ca; v.z *= ca; v.w *= ca;
        *(float4*)(op + p) = v;
    }
}

// ---------- content_lambda phase 1: per-512-col partial online softmax ----------
__global__ void k_lambda_part() {
    int blk = blockIdx.x;
    int bh = blk >> 3, chunk = blk & 7;
    int b = bh >> 3, nh = bh & 7;
    const float* kbase = g_qkv + ((size_t)b * OC3 + CC + nh * HDIM) * HW + chunk * 512;
    const float* vbase = g_qkv + ((size_t)b * OC3 + 2 * CC + nh * HDIM) * HW + chunk * 512;
    __shared__ float ks[HDIM][129];
    __shared__ float vs[HDIM][129];
    int tid = threadIdx.x;
    int i = tid >> 4, o = tid & 15;
    float m = -1e30f, d = 0.f, acc = 0.f;
    for (int c0 = 0; c0 < 512; c0 += 128) {
        for (int t = tid; t < HDIM * 128; t += 256) {
            int r = t >> 7, j = t & 127;
            ks[r][j] = kbase[(size_t)r * HW + c0 + j];
            vs[r][j] = vbase[(size_t)r * HW + c0 + j];
        }
        __syncthreads();
        float mc = -1e30f;
#pragma unroll
        for (int t = 0; t < 8; t++) mc = fmaxf(mc, ks[i][o + t * 16]);
#pragma unroll
        for (int msk = 1; msk < 16; msk <<= 1)
            mc = fmaxf(mc, __shfl_xor_sync(0xffffffffu, mc, msk));
        float mnew = fmaxf(m, mc);
        float corr = expf(m - mnew);
        d *= corr; acc *= corr;
        float ps = 0.f;
#pragma unroll
        for (int t = 0; t < 8; t++) {
            float e = expf(ks[i][o + t * 16] - mnew);
            ks[i][o + t * 16] = e;
            ps += e;
        }
#pragma unroll
        for (int msk = 1; msk < 16; msk <<= 1)
            ps += __shfl_xor_sync(0xffffffffu, ps, msk);
        d += ps;
        m = mnew;
        __syncwarp();
#pragma unroll 8
        for (int j = 0; j < 128; j++) acc += ks[i][j] * vs[o][j];
        __syncthreads();
    }
    g_lacc[blk * 256 + tid] = acc;
    if (o == 0) {
        g_lm[blk * HDIM + i] = m;
        g_ld[blk * HDIM + i] = d;
    }
}

// ---------- content_lambda phase 2: merge 8 partials ----------
__global__ void k_lambda_merge() {
    int bh = blockIdx.x;
    int tid = threadIdx.x;
    int i = tid >> 4;
    float M = -1e30f;
#pragma unroll
    for (int c = 0; c < 8; c++) M = fmaxf(M, g_lm[(bh * 8 + c) * HDIM + i]);
    float acc = 0.f, d = 0.f;
#pragma unroll
    for (int c = 0; c < 8; c++) {
        float w = expf(g_lm[(bh * 8 + c) * HDIM + i] - M);
        acc += g_lacc[(bh * 8 + c) * 256 + tid] * w;
        d += g_ld[(bh * 8 + c) * HDIM + i] * w;
    }
    g_lam[bh * 256 + tid] = acc / d;
}

// ---------------- position lambda: depthwise 5x5 of v ----------------
__global__ void k_pos(const float* __restrict__ rel) {
    int bc = blockIdx.x;
    int b = bc >> 7, c = bc & 127;
    const float* vp = g_qkv + ((size_t)b * OC3 + 2 * CC + c) * HW;
    const float* w = rel + (c & 15) * 25;
    __shared__ float t[68][68];
    for (int i = threadIdx.x; i < 68 * 68; i += blockDim.x) {
        int r = i / 68, q = i % 68;
        int rr = r - 2, qq = q - 2;
        t[r][q] = (rr >= 0 && rr < 64 && qq >= 0 && qq < 64) ? vp[rr * 64 + qq] : 0.f;
    }
    __syncthreads();
    float wr[25];
#pragma unroll
    for (int j = 0; j < 25; j++) wr[j] = w[j];
    for (int p = threadIdx.x; p < HW; p += blockDim.x) {
        int r = p >> 6, q = p & 63;
        float acc = 0.f;
#pragma unroll
        for (int dr = 0; dr < 5; dr++)
#pragma unroll
            for (int dc = 0; dc < 5; dc++)
                acc += wr[dr * 5 + dc] * t[r + dr][q + dc];
        g_poslam[(size_t)bc * HW + p] = acc;
    }
}

// ---------------- combine: cat[0:128] = 0.25 * (q^T lam) + q * poslam ----------------
__global__ void k_combine() {
    int bh = blockIdx.y;
    int b = bh >> 3, nh = bh & 7;
    int n = blockIdx.x * 256 + threadIdx.x;
    __shared__ float lam[HDIM][HDIM + 1];
    lam[threadIdx.x >> 4][threadIdx.x & 15] = g_lam[bh * 256 + threadIdx.x];
    __syncthreads();
    const float* qbase = g_qkv + ((size_t)b * OC3 + nh * HDIM) * HW;
    const float* plbase = g_poslam + (size_t)(b * CC + nh * HDIM) * HW;
    float* rbase = g_cat + ((size_t)b * 2 * CC + nh * HDIM) * HW;
    float qv[16];
#pragma unroll
    for (int i = 0; i < 16; i++) qv[i] = qbase[(size_t)i * HW + n];
    const float scaling = 0.25f;  // HD^-0.5
#pragma unroll
    for (int o = 0; o < 16; o++) {
        float cacc = 0.f;
#pragma unroll
        for (int i = 0; i < 16; i++) cacc += qv[i] * lam[i][o];
        rbase[(size_t)o * HW + n] = cacc * scaling + qv[o] * plbase[(size_t)o * HW + n];
    }
}

extern "C" void kernel_launch(void* const* d_in, const int* in_sizes, int n_in,
                              void* d_out, int out_size) {
    const float* src    = (const float*)d_in[0];  // (16,128,64,64)
    const float* cpe_w  = (const float*)d_in[1];  // (128,1,3,3)
    const float* qkv_w  = (const float*)d_in[2];  // (384,128)
    const float* rel    = (const float*)d_in[3];  // (16,5,5)
    const float* c1d    = (const float*)d_in[4];  // (3,)
    const float* out_w  = (const float*)d_in[5];  // (512,256)
    float* out = (float*)d_out;                   // (16,512,64,64)

    cudaFuncSetAttribute(k_gemm, cudaFuncAttributeMaxDynamicSharedMemorySize, GEMM_SMEM);

    float* d_s;      cudaGetSymbolAddress((void**)&d_s, g_s);
    float* d_qkv;    cudaGetSymbolAddress((void**)&d_qkv, g_qkv);
    float* d_cat;    cudaGetSymbolAddress((void**)&d_cat, g_cat);
    float* d_wqkvT;  cudaGetSymbolAddress((void**)&d_wqkvT, g_wqkvT);
    float* d_woutT;  cudaGetSymbolAddress((void**)&d_woutT, g_woutT);

    k_transpose_all<<<(OC3 * CC + OUTC * 2 * CC + 255) / 256, 256>>>(qkv_w, out_w);
    k_cpe<<<BB * CC, 256>>>(src, cpe_w);
    k_scale<<<BB * CC, 256>>>(src, c1d);
    // QKV GEMM: M=384, N=4096, K=128
    k_gemm<<<dim3(HW / 128, OC3 / 128, BB), 256, GEMM_SMEM>>>(d_wqkvT, d_s, d_qkv, CC, OC3);
    k_lambda_part<<<BH * 8, 256>>>();
    k_lambda_merge<<<BH, 256>>>();
    k_pos<<<BB * CC, 256>>>(rel);
    k_combine<<<dim3(HW / 256, BH), 256>>>();
    // Final GEMM: M=512, N=4096, K=256 over g_cat
    k_gemm<<<dim3(HW / 128, OUTC / 128, BB), 256, GEMM_SMEM>>>(d_woutT, d_cat, out, 2 * CC, OUTC);
}